// round 1
// baseline (speedup 1.0000x reference)
#include <cuda_runtime.h>

// Shapes fixed by the problem: B=2, H=8, L=S=2048, D=64, fp32.
#define Dh       64
#define Ls       2048
#define ROWS     16      // query rows per block
#define CT       256     // column-tile width
#define NTHREADS 256
#define XS       17      // float4 row stride for D-vectors (68 floats, padded)
#define VTS      65      // float4 row stride for transposed V tile (260 floats)

#define SMEM_FLOATS (ROWS*68 + CT*68 + ROWS*Ls)   // 1088 + 17408 + 32768 = 51264
#define SMEM_BYTES  (SMEM_FLOATS * 4)             // 205056

#define DOT4(a,b) ((a).x*(b).x + (a).y*(b).y + (a).z*(b).z + (a).w*(b).w)

// Compute S[r][c] = (row_r . col_c) * 0.125 for r in [0,16), c in [0,2048),
// into sS (row-major, stride Ls), then row-softmax in place.
__device__ __forceinline__ void scores_softmax(const float* __restrict__ rowptr,
                                               const float* __restrict__ colptr,
                                               float* sX, float* sC, float* sS,
                                               int tid)
{
    float4* sX4 = (float4*)sX;
    float4* sC4 = (float4*)sC;
    const float4* rg4 = (const float4*)rowptr;

    // load 16 row vectors (16 x 64 floats) into padded smem
    for (int idx = tid; idx < ROWS * (Dh/4); idx += NTHREADS) {
        int r = idx >> 4, d4 = idx & 15;
        sX4[r * XS + d4] = rg4[r * 16 + d4];
    }

    const int rgrp = tid >> 6;   // 0..3 -> rows rgrp*4 .. +4
    const int cg   = tid & 63;   // cols cg + 64*j

    for (int ct = 0; ct < Ls / CT; ++ct) {
        __syncthreads();
        const float4* cgl = (const float4*)colptr + (long)ct * CT * (Dh/4);
        for (int idx = tid; idx < CT * (Dh/4); idx += NTHREADS) {
            int c = idx >> 4, d4 = idx & 15;
            sC4[c * XS + d4] = cgl[idx];
        }
        __syncthreads();

        float acc[4][4];
        #pragma unroll
        for (int i = 0; i < 4; ++i)
            #pragma unroll
            for (int j = 0; j < 4; ++j) acc[i][j] = 0.f;

        #pragma unroll
        for (int kq = 0; kq < 16; ++kq) {
            float4 x0 = sX4[(rgrp*4+0)*XS + kq];
            float4 x1 = sX4[(rgrp*4+1)*XS + kq];
            float4 x2 = sX4[(rgrp*4+2)*XS + kq];
            float4 x3 = sX4[(rgrp*4+3)*XS + kq];
            float4 y0 = sC4[(cg      )*XS + kq];
            float4 y1 = sC4[(cg +  64)*XS + kq];
            float4 y2 = sC4[(cg + 128)*XS + kq];
            float4 y3 = sC4[(cg + 192)*XS + kq];
            acc[0][0] += DOT4(x0,y0); acc[0][1] += DOT4(x0,y1);
            acc[0][2] += DOT4(x0,y2); acc[0][3] += DOT4(x0,y3);
            acc[1][0] += DOT4(x1,y0); acc[1][1] += DOT4(x1,y1);
            acc[1][2] += DOT4(x1,y2); acc[1][3] += DOT4(x1,y3);
            acc[2][0] += DOT4(x2,y0); acc[2][1] += DOT4(x2,y1);
            acc[2][2] += DOT4(x2,y2); acc[2][3] += DOT4(x2,y3);
            acc[3][0] += DOT4(x3,y0); acc[3][1] += DOT4(x3,y1);
            acc[3][2] += DOT4(x3,y2); acc[3][3] += DOT4(x3,y3);
        }

        #pragma unroll
        for (int i = 0; i < 4; ++i)
            #pragma unroll
            for (int j = 0; j < 4; ++j)
                sS[(rgrp*4+i)*Ls + ct*CT + cg + 64*j] = acc[i][j] * 0.125f;
    }
    __syncthreads();

    // row softmax: 8 warps, 2 rows each
    const int warp = tid >> 5, lane = tid & 31;
    for (int r = warp; r < ROWS; r += 8) {
        float* row = sS + r * Ls;
        float m = -1e30f;
        for (int t = lane; t < Ls; t += 32) m = fmaxf(m, row[t]);
        #pragma unroll
        for (int o = 16; o; o >>= 1) m = fmaxf(m, __shfl_xor_sync(0xffffffffu, m, o));
        float s = 0.f;
        for (int t = lane; t < Ls; t += 32) {
            float e = __expf(row[t] - m);
            row[t] = e;
            s += e;
        }
        #pragma unroll
        for (int o = 16; o; o >>= 1) s += __shfl_xor_sync(0xffffffffu, s, o);
        float inv = 1.0f / s;
        for (int t = lane; t < Ls; t += 32) row[t] *= inv;
    }
    __syncthreads();
}

// softmax(X Xᵀ / 8) rows -> write (add==0) or += (add==1) into attn output.
__global__ void __launch_bounds__(NTHREADS, 1)
attn_weight_kernel(const float* __restrict__ X, float* __restrict__ outAttn, int add)
{
    extern __shared__ float smem[];
    float* sX = smem;
    float* sC = smem + ROWS*68;
    float* sS = smem + ROWS*68 + CT*68;
    const int tid = threadIdx.x;
    const int bh  = blockIdx.x >> 7;
    const int l0  = (blockIdx.x & 127) * ROWS;

    const float* base = X + (long)bh * Ls * Dh;
    scores_softmax(base + (long)l0 * Dh, base, sX, sC, sS, tid);

    const float4* sS4 = (const float4*)sS;
    float4* o4 = (float4*)(outAttn + ((long)(bh * Ls + l0)) * Ls);
    if (add) {
        for (int idx = tid; idx < ROWS * (Ls/4); idx += NTHREADS) {
            float4 v = sS4[idx];
            float4 o = o4[idx];
            o.x += v.x; o.y += v.y; o.z += v.z; o.w += v.w;
            o4[idx] = o;
        }
    } else {
        for (int idx = tid; idx < ROWS * (Ls/4); idx += NTHREADS)
            o4[idx] = sS4[idx];
    }
}

// out = softmax(Q Kᵀ / 8) · V
__global__ void __launch_bounds__(NTHREADS, 1)
sdpa_kernel(const float* __restrict__ Q, const float* __restrict__ K,
            const float* __restrict__ V, float* __restrict__ outO)
{
    extern __shared__ float smem[];
    float* sX = smem;
    float* sC = smem + ROWS*68;
    float* sS = smem + ROWS*68 + CT*68;
    const int tid = threadIdx.x;
    const int bh  = blockIdx.x >> 7;
    const int l0  = (blockIdx.x & 127) * ROWS;

    const float* qb = Q + (long)bh * Ls * Dh;
    const float* kb = K + (long)bh * Ls * Dh;
    const float* vb = V + (long)bh * Ls * Dh;

    scores_softmax(qb + (long)l0 * Dh, kb, sX, sC, sS, tid);

    // P·V: probabilities in sS, V tiles transposed into sC region.
    const int jg  = tid >> 6;       // split-K group 0..3
    const int pos = tid & 63;
    const int prg = pos >> 5;       // row group 0..1 -> rows prg*8..+8
    const int dg  = pos & 31;       // d columns dg and dg+32

    float acc[8][2];
    #pragma unroll
    for (int i = 0; i < 8; ++i) { acc[i][0] = 0.f; acc[i][1] = 0.f; }

    const float4* sS4  = (const float4*)sS;
    const float4* sVT4 = (const float4*)sC;
    const float4* vg4  = (const float4*)vb;

    for (int kt = 0; kt < Ls / CT; ++kt) {
        __syncthreads();
        for (int idx = tid; idx < CT * 16; idx += NTHREADS) {
            int j = idx >> 4, d4 = idx & 15;
            float4 v = vg4[(long)(kt * CT + j) * 16 + d4];
            sC[(d4*4 + 0) * 260 + j] = v.x;
            sC[(d4*4 + 1) * 260 + j] = v.y;
            sC[(d4*4 + 2) * 260 + j] = v.z;
            sC[(d4*4 + 3) * 260 + j] = v.w;
        }
        __syncthreads();

        #pragma unroll 4
        for (int j = jg * 64; j < jg * 64 + 64; j += 4) {
            int jq = (kt * CT + j) >> 2;       // global column quad for P
            int jl = j >> 2;                    // local column quad for V tile
            float4 v0 = sVT4[ dg       * VTS + jl];
            float4 v1 = sVT4[(dg + 32) * VTS + jl];
            #pragma unroll
            for (int i = 0; i < 8; ++i) {
                float4 p = sS4[(prg*8 + i) * (Ls/4) + jq];
                acc[i][0] += DOT4(p, v0);
                acc[i][1] += DOT4(p, v1);
            }
        }
    }

    // reduce 4 split-K partials via smem (reuse sC)
    __syncthreads();
    float* red = sC;
    #pragma unroll
    for (int i = 0; i < 8; ++i) {
        red[jg*1024 + (prg*8 + i)*64 + dg     ] = acc[i][0];
        red[jg*1024 + (prg*8 + i)*64 + dg + 32] = acc[i][1];
    }
    __syncthreads();

    float* outp = outO + ((long)(bh * Ls + l0)) * Dh;
    for (int idx = tid; idx < ROWS * Dh; idx += NTHREADS)
        outp[idx] = red[idx] + red[1024 + idx] + red[2048 + idx] + red[3072 + idx];
}

extern "C" void kernel_launch(void* const* d_in, const int* in_sizes, int n_in,
                              void* d_out, int out_size)
{
    const float* q = (const float*)d_in[0];
    const float* k = (const float*)d_in[1];
    const float* v = (const float*)d_in[2];

    float* outO    = (float*)d_out;                 // [2,8,2048,64]   = 2097152
    float* outAttn = (float*)d_out + 2097152;       // [2,8,2048,2048] = 67108864

    cudaFuncSetAttribute(attn_weight_kernel,
                         cudaFuncAttributeMaxDynamicSharedMemorySize, SMEM_BYTES);
    cudaFuncSetAttribute(sdpa_kernel,
                         cudaFuncAttributeMaxDynamicSharedMemorySize, SMEM_BYTES);

    const int grid = 16 * (Ls / ROWS);  // 16 bh * 128 row-tiles = 2048

    attn_weight_kernel<<<grid, NTHREADS, SMEM_BYTES>>>(q, outAttn, 0);
    attn_weight_kernel<<<grid, NTHREADS, SMEM_BYTES>>>(k, outAttn, 1);
    sdpa_kernel<<<grid, NTHREADS, SMEM_BYTES>>>(q, k, v, outO);
}